// round 4
// baseline (speedup 1.0000x reference)
#include <cuda_runtime.h>
#include <math.h>

#define Bb 256
#define Nn 1000
#define Dd 512
#define NEGINF (-INFINITY)
#define NORM_MHA 0.125f
#define NORM_PTR 0.04419417382415922f

static __device__ float g_state[Bb * Dd];
static __device__ float g_Qf[Bb * Dd];
static __device__ float g_Qt[Bb * 8 * Dd];
static __device__ float g_ysum[Bb * 8 * Dd];
static __device__ float g_l[Bb * 8];
static __device__ float g_mhaH[Bb * Dd];
static __device__ float g_mo[Bb * Dd];
static __device__ float g_z[Bb * Dd];

// state = [x0,dc]@W_fc + pool@W_fc1 ; grid(4,32) x 128
__global__ void __launch_bounds__(128) kS(const float* __restrict__ X, const float* __restrict__ pool,
                                          const float* __restrict__ dc, const float* __restrict__ Wfc,
                                          const float* __restrict__ Wfc1) {
    __shared__ float sx[512 * 8], sp[512 * 8], sdc[8];
    int j0 = blockIdx.x * 128, b0 = blockIdx.y * 8, tid = threadIdx.x;
    for (int i = tid; i < 4096; i += 128) {
        int bb = i >> 9, e = i & 511;
        sx[e * 8 + bb] = X[(size_t)(b0 + bb) * (Nn * Dd) + e];
        sp[e * 8 + bb] = pool[(b0 + bb) * Dd + e];
    }
    if (tid < 8) sdc[tid] = dc[b0 + tid];
    __syncthreads();
    int j = j0 + tid;
    float acc[8] = {0, 0, 0, 0, 0, 0, 0, 0};
    for (int e = 0; e < 512; e++) {
        float w0 = Wfc[e * Dd + j], w1 = Wfc1[e * Dd + j];
        float4 a0 = *(const float4*)(sx + e * 8), a1 = *(const float4*)(sx + e * 8 + 4);
        float4 c0 = *(const float4*)(sp + e * 8), c1 = *(const float4*)(sp + e * 8 + 4);
        acc[0] += a0.x * w0 + c0.x * w1; acc[1] += a0.y * w0 + c0.y * w1;
        acc[2] += a0.z * w0 + c0.z * w1; acc[3] += a0.w * w0 + c0.w * w1;
        acc[4] += a1.x * w0 + c1.x * w1; acc[5] += a1.y * w0 + c1.y * w1;
        acc[6] += a1.z * w0 + c1.z * w1; acc[7] += a1.w * w0 + c1.w * w1;
    }
    float wl = Wfc[512 * Dd + j];
#pragma unroll
    for (int bb = 0; bb < 8; bb++) g_state[(b0 + bb) * Dd + j] = acc[bb] + sdc[bb] * wl;
}

// Out[b][j] = sum_f A[b][f]*W[f][j] ; mode0: state->Qf ; mode1: mhaH->mo
__global__ void __launch_bounds__(128) kMM(const float* __restrict__ W, int mode) {
    __shared__ float sa[512 * 8];
    const float* A = mode ? g_mhaH : g_state;
    float* Out = mode ? g_mo : g_Qf;
    int j0 = blockIdx.x * 128, b0 = blockIdx.y * 8, tid = threadIdx.x;
    for (int i = tid; i < 4096; i += 128) sa[(i & 511) * 8 + (i >> 9)] = A[(b0 + (i >> 9)) * Dd + (i & 511)];
    __syncthreads();
    int j = j0 + tid;
    float acc[8] = {0, 0, 0, 0, 0, 0, 0, 0};
    for (int f = 0; f < 512; f++) {
        float w = W[f * Dd + j];
        float4 a0 = *(const float4*)(sa + f * 8), a1 = *(const float4*)(sa + f * 8 + 4);
        acc[0] += a0.x * w; acc[1] += a0.y * w; acc[2] += a0.z * w; acc[3] += a0.w * w;
        acc[4] += a1.x * w; acc[5] += a1.y * w; acc[6] += a1.z * w; acc[7] += a1.w * w;
    }
#pragma unroll
    for (int bb = 0; bb < 8; bb++) Out[(b0 + bb) * Dd + j] = acc[bb];
}

// Qt[b][h][e] = norm_mha * sum_d Wk[e][h*64+d]*Qf[b][h*64+d]
__global__ void __launch_bounds__(128) kQt(const float* __restrict__ Wk) {
    __shared__ float sq[8 * 512];
    int e0 = blockIdx.x * 128, b0 = blockIdx.y * 8, tid = threadIdx.x;
    for (int i = tid; i < 4096; i += 128) sq[i] = g_Qf[(b0 + (i >> 9)) * Dd + (i & 511)];
    __syncthreads();
    int e = e0 + tid;
    const float* wrow = Wk + (size_t)e * Dd;
    for (int h = 0; h < 8; h++) {
        float acc[8] = {0, 0, 0, 0, 0, 0, 0, 0};
        const float* wr = wrow + h * 64;
#pragma unroll
        for (int d4 = 0; d4 < 16; d4++) {
            float4 wv = *(const float4*)(wr + d4 * 4);
#pragma unroll
            for (int bb = 0; bb < 8; bb++) {
                float4 q = *(const float4*)(sq + bb * 512 + h * 64 + d4 * 4);
                acc[bb] += wv.x * q.x + wv.y * q.y + wv.z * q.z + wv.w * q.w;
            }
        }
#pragma unroll
        for (int bb = 0; bb < 8; bb++) g_Qt[(size_t)(b0 + bb) * 4096 + h * 512 + e] = acc[bb] * NORM_MHA;
    }
}

// main streaming pass: compat + online softmax + weighted token sum ; grid 256 x 512
__global__ void __launch_bounds__(512, 2) kB(const float* __restrict__ X, const int* __restrict__ mask) {
    __shared__ float xs[16 * 512];
    __shared__ float cpart[2 * 16 * 8];
    __shared__ float pbuf[16 * 8];
    __shared__ float s_m[8], s_l[8], s_scale[8], s_any;
    __shared__ int s_mask[16];
    int b = blockIdx.x, tid = threadIdx.x, w = tid >> 5, lane = tid & 31;
    int tg = w >> 2, qh = (w >> 1) & 1, eh = w & 1;
    int e_lo = eh * 256 + (lane << 2);
    float qt[4][8];
    {
        const float* Qtb = g_Qt + (size_t)b * 4096;
#pragma unroll
        for (int hh = 0; hh < 4; hh++) {
            int h = qh * 4 + hh;
            float4 a = *(const float4*)(Qtb + h * 512 + e_lo);
            float4 c = *(const float4*)(Qtb + h * 512 + e_lo + 128);
            qt[hh][0] = a.x; qt[hh][1] = a.y; qt[hh][2] = a.z; qt[hh][3] = a.w;
            qt[hh][4] = c.x; qt[hh][5] = c.y; qt[hh][6] = c.z; qt[hh][7] = c.w;
        }
    }
    int grp = tid >> 8, e2 = tid & 255;
    float ys[8][2];
#pragma unroll
    for (int h = 0; h < 8; h++) { ys[h][0] = 0.f; ys[h][1] = 0.f; }
    if (tid < 8) { s_m[tid] = NEGINF; s_l[tid] = 0.f; }
    const float* Xb = X + (size_t)b * (Nn * Dd);
    const int* mb = mask + b * Nn;

    for (int t0 = 0; t0 < Nn; t0 += 16) {
        int ntok = min(16, Nn - t0);
        const float4* src = (const float4*)(Xb + (size_t)t0 * Dd);
        float4* dst = (float4*)xs;
        int nv = ntok * 128;
        for (int i = tid; i < nv; i += 512) dst[i] = src[i];
        if (tid < ntok) s_mask[tid] = mb[t0 + tid];
        if (tid == 0) s_any = 0.f;
        __syncthreads();
        if (tg * 4 < ntok) {
#pragma unroll
            for (int k = 0; k < 4; k++) {
                int n = tg * 4 + k;
                const float* row = xs + (n << 9);
                float4 xa = *(const float4*)(row + e_lo);
                float4 xbv = *(const float4*)(row + e_lo + 128);
                float av[4];
#pragma unroll
                for (int hh = 0; hh < 4; hh++)
                    av[hh] = xa.x * qt[hh][0] + xa.y * qt[hh][1] + xa.z * qt[hh][2] + xa.w * qt[hh][3]
                           + xbv.x * qt[hh][4] + xbv.y * qt[hh][5] + xbv.z * qt[hh][6] + xbv.w * qt[hh][7];
#pragma unroll
                for (int off = 16; off > 0; off >>= 1)
#pragma unroll
                    for (int hh = 0; hh < 4; hh++) av[hh] += __shfl_xor_sync(0xffffffffu, av[hh], off);
                if (lane == 0)
                    *(float4*)(cpart + (eh * 16 + n) * 8 + qh * 4) = make_float4(av[0], av[1], av[2], av[3]);
            }
        }
        __syncthreads();
        if (w < 8) {
            int h = w;
            float u = NEGINF;
            if (lane < ntok && s_mask[lane] == 0) u = cpart[lane * 8 + h] + cpart[128 + lane * 8 + h];
            float tmax = u;
#pragma unroll
            for (int off = 16; off > 0; off >>= 1) tmax = fmaxf(tmax, __shfl_xor_sync(0xffffffffu, tmax, off));
            float m_old = s_m[h], m_new = fmaxf(m_old, tmax);
            float p = (u != NEGINF) ? __expf(u - m_new) : 0.f;
            if (lane < 16) pbuf[lane * 8 + h] = p;
            float ps = p;
#pragma unroll
            for (int off = 16; off > 0; off >>= 1) ps += __shfl_xor_sync(0xffffffffu, ps, off);
            if (lane == 0) {
                float sc = 1.f;
                if (m_new > m_old) { sc = (m_old == NEGINF) ? 1.f : __expf(m_old - m_new); s_m[h] = m_new; }
                s_scale[h] = sc;
                s_l[h] = s_l[h] * sc + ps;
                if (sc != 1.f) s_any = 1.f;
            }
        }
        __syncthreads();
        if (s_any != 0.f) {
#pragma unroll
            for (int h = 0; h < 8; h++) { float sc = s_scale[h]; ys[h][0] *= sc; ys[h][1] *= sc; }
        }
        int kend = grp * 8 + 8;
        if (kend > ntok) kend = ntok;
        for (int k = grp * 8; k < kend; k++) {
            float2 xv = *(const float2*)(xs + (k << 9) + (e2 << 1));
            float4 p0 = *(const float4*)(pbuf + (k << 3));
            float4 p1 = *(const float4*)(pbuf + (k << 3) + 4);
            ys[0][0] += p0.x * xv.x; ys[0][1] += p0.x * xv.y;
            ys[1][0] += p0.y * xv.x; ys[1][1] += p0.y * xv.y;
            ys[2][0] += p0.z * xv.x; ys[2][1] += p0.z * xv.y;
            ys[3][0] += p0.w * xv.x; ys[3][1] += p0.w * xv.y;
            ys[4][0] += p1.x * xv.x; ys[4][1] += p1.x * xv.y;
            ys[5][0] += p1.y * xv.x; ys[5][1] += p1.y * xv.y;
            ys[6][0] += p1.z * xv.x; ys[6][1] += p1.z * xv.y;
            ys[7][0] += p1.w * xv.x; ys[7][1] += p1.w * xv.y;
        }
        __syncthreads();
    }
    float* buf = xs;
    if (grp == 0) {
#pragma unroll
        for (int h = 0; h < 8; h++) *(float2*)(buf + h * 512 + (e2 << 1)) = make_float2(ys[h][0], ys[h][1]);
    }
    __syncthreads();
    if (grp == 1) {
#pragma unroll
        for (int h = 0; h < 8; h++) {
            float2 v = *(float2*)(buf + h * 512 + (e2 << 1));
            v.x += ys[h][0]; v.y += ys[h][1];
            *(float2*)(buf + h * 512 + (e2 << 1)) = v;
        }
    }
    __syncthreads();
    float* yo = g_ysum + (size_t)b * 4096;
    for (int i = tid; i < 4096; i += 512) yo[i] = buf[i];
    if (tid < 8) g_l[b * 8 + tid] = s_l[tid];
}

// mhaH[b][g] = sum_e (ysum[b][g>>6][e]/l)*Wv[e][g]
__global__ void __launch_bounds__(128) kV(const float* __restrict__ Wv) {
    __shared__ float syc[2 * 4096];
    __shared__ float slinv[16];
    int h0 = blockIdx.x * 2, b0 = blockIdx.y * 8, tid = threadIdx.x;
    if (tid < 16) slinv[tid] = 1.f / g_l[(b0 + (tid >> 1)) * 8 + h0 + (tid & 1)];
    __syncthreads();
    for (int i = tid; i < 8192; i += 128) {
        int hl = i >> 12, bb = (i >> 9) & 7, e = i & 511;
        syc[hl * 4096 + e * 8 + bb] = g_ysum[(size_t)(b0 + bb) * 4096 + (h0 + hl) * 512 + e] * slinv[bb * 2 + hl];
    }
    __syncthreads();
    int j = blockIdx.x * 128 + tid, hl = tid >> 6;
    const float* base = syc + hl * 4096;
    float acc[8] = {0, 0, 0, 0, 0, 0, 0, 0};
    for (int e = 0; e < 512; e++) {
        float w = Wv[e * Dd + j];
        float4 y0 = *(const float4*)(base + e * 8), y1 = *(const float4*)(base + e * 8 + 4);
        acc[0] += y0.x * w; acc[1] += y0.y * w; acc[2] += y0.z * w; acc[3] += y0.w * w;
        acc[4] += y1.x * w; acc[5] += y1.y * w; acc[6] += y1.z * w; acc[7] += y1.w * w;
    }
#pragma unroll
    for (int bb = 0; bb < 8; bb++) g_mhaH[(b0 + bb) * Dd + j] = acc[bb];
}

// z[b][e] = norm_ptr * sum_f Wkp[e][f]*mo[b][f]
__global__ void __launch_bounds__(128) kZ(const float* __restrict__ Wkp) {
    __shared__ float smo[512 * 8];
    int e0 = blockIdx.x * 128, b0 = blockIdx.y * 8, tid = threadIdx.x;
    for (int i = tid; i < 4096; i += 128) smo[(i & 511) * 8 + (i >> 9)] = g_mo[(b0 + (i >> 9)) * Dd + (i & 511)];
    __syncthreads();
    int e = e0 + tid;
    const float* wrow = Wkp + (size_t)e * Dd;
    float acc[8] = {0, 0, 0, 0, 0, 0, 0, 0};
    for (int f = 0; f < 512; f++) {
        float w = wrow[f];
        float4 m0 = *(const float4*)(smo + f * 8), m1 = *(const float4*)(smo + f * 8 + 4);
        acc[0] += m0.x * w; acc[1] += m0.y * w; acc[2] += m0.z * w; acc[3] += m0.w * w;
        acc[4] += m1.x * w; acc[5] += m1.y * w; acc[6] += m1.z * w; acc[7] += m1.w * w;
    }
#pragma unroll
    for (int bb = 0; bb < 8; bb++) g_z[(b0 + bb) * Dd + e] = acc[bb] * NORM_PTR;
}

// second streaming pass: tanh(x.z)*10, masked softmax ; grid 256 x 512
__global__ void __launch_bounds__(512, 2) kD(const float* __restrict__ X, const int* __restrict__ mask,
                                             float* __restrict__ out) {
    __shared__ float tvals[Nn];
    __shared__ float red[16];
    __shared__ float bcast;
    int b = blockIdx.x, tid = threadIdx.x, w = tid >> 5, lane = tid & 31;
    const float* zb = g_z + b * Dd;
    float4 z0 = *(const float4*)(zb + lane * 4);
    float4 z1 = *(const float4*)(zb + 128 + lane * 4);
    float4 z2 = *(const float4*)(zb + 256 + lane * 4);
    float4 z3 = *(const float4*)(zb + 384 + lane * 4);
    const float* Xb = X + (size_t)b * (Nn * Dd);
    const int* mb = mask + b * Nn;
    float wmax = NEGINF;
    for (int n = w; n < Nn; n += 16) {
        const float* row = Xb + (size_t)n * Dd;
        float4 x0 = *(const float4*)(row + lane * 4);
        float4 x1 = *(const float4*)(row + 128 + lane * 4);
        float4 x2 = *(const float4*)(row + 256 + lane * 4);
        float4 x3 = *(const float4*)(row + 384 + lane * 4);
        float acc = x0.x * z0.x + x0.y * z0.y + x0.z * z0.z + x0.w * z0.w
                  + x1.x * z1.x + x1.y * z1.y + x1.z * z1.z + x1.w * z1.w
                  + x2.x * z2.x + x2.y * z2.y + x2.z * z2.z + x2.w * z2.w
                  + x3.x * z3.x + x3.y * z3.y + x3.z * z3.z + x3.w * z3.w;
#pragma unroll
        for (int off = 16; off > 0; off >>= 1) acc += __shfl_xor_sync(0xffffffffu, acc, off);
        float tv = tanhf(acc) * 10.f;
        if (mb[n] != 0) tv = NEGINF;
        if (lane == 0) tvals[n] = tv;
        wmax = fmaxf(wmax, tv);
    }
    if (lane == 0) red[w] = wmax;
    __syncthreads();
    if (tid == 0) {
        float m = red[0];
#pragma unroll
        for (int i = 1; i < 16; i++) m = fmaxf(m, red[i]);
        bcast = m;
    }
    __syncthreads();
    float gmax = bcast;
    float t0v = tvals[tid];
    float ev0 = (t0v == NEGINF) ? 0.f : __expf(t0v - gmax);
    int n1 = tid + 512;
    float ev1 = 0.f;
    if (n1 < Nn) {
        float t1v = tvals[n1];
        ev1 = (t1v == NEGINF) ? 0.f : __expf(t1v - gmax);
    }
    float ps = ev0 + ev1;
#pragma unroll
    for (int off = 16; off > 0; off >>= 1) ps += __shfl_xor_sync(0xffffffffu, ps, off);
    __syncthreads();
    if (lane == 0) red[w] = ps;
    __syncthreads();
    if (tid == 0) {
        float s = 0.f;
#pragma unroll
        for (int i = 0; i < 16; i++) s += red[i];
        bcast = 1.f / s;
    }
    __syncthreads();
    float inv = bcast;
    out[b * Nn + tid] = ev0 * inv;
    if (n1 < Nn) out[b * Nn + n1] = ev1 * inv;
}

extern "C" void kernel_launch(void* const* d_in, const int* in_sizes, int n_in,
                              void* d_out, int out_size) {
    const float* X    = (const float*)d_in[0];
    const float* pool = (const float*)d_in[1];
    const float* dc   = (const float*)d_in[2];
    const int*   mask = (const int*)d_in[3];
    const float* Wfc  = (const float*)d_in[4];
    const float* Wfc1 = (const float*)d_in[5];
    const float* Wq   = (const float*)d_in[6];
    const float* Wkm  = (const float*)d_in[7];
    const float* Wv   = (const float*)d_in[8];
    const float* Wo   = (const float*)d_in[9];
    const float* Wkp  = (const float*)d_in[10];
    float* out = (float*)d_out;
    dim3 g(4, 32);
    kS<<<g, 128>>>(X, pool, dc, Wfc, Wfc1);
    kMM<<<g, 128>>>(Wq, 0);
    kQt<<<g, 128>>>(Wkm);
    kB<<<256, 512>>>(X, mask);
    kV<<<g, 128>>>(Wv);
    kMM<<<g, 128>>>(Wo, 1);
    kZ<<<g, 128>>>(Wkp);
    kD<<<256, 512>>>(X, mask, out);
}

// round 7
// speedup vs baseline: 1.4233x; 1.4233x over previous
#include <cuda_runtime.h>
#include <math.h>
#include <stdint.h>

#define Bb 256
#define Nn 1000
#define Dd 512
#define NEGINF (-INFINITY)
#define NORM_MHA 0.125f
#define NORM_PTR 0.04419417382415922f

static __device__ float g_state[Bb * Dd];
static __device__ float g_Qf[Bb * Dd];
static __device__ float g_Qt[Bb * 8 * Dd];
static __device__ float g_ysum[Bb * 8 * Dd];
static __device__ float g_l[Bb * 8];
static __device__ float g_mhaH[Bb * Dd];
static __device__ float g_mo[Bb * Dd];
static __device__ float g_z[Bb * Dd];

// ---------- f32x2 + cp.async helpers ----------
__device__ __forceinline__ unsigned long long pack2(float a, float b) {
    unsigned long long r;
    asm("mov.b64 %0,{%1,%2};" : "=l"(r) : "f"(a), "f"(b));
    return r;
}
__device__ __forceinline__ void unpack2(unsigned long long v, float& a, float& b) {
    asm("mov.b64 {%0,%1},%2;" : "=f"(a), "=f"(b) : "l"(v));
}
__device__ __forceinline__ void ffma2(unsigned long long& d, unsigned long long a, unsigned long long b) {
    asm("fma.rn.f32x2 %0,%1,%2,%0;" : "+l"(d) : "l"(a), "l"(b));
}
__device__ __forceinline__ void fmul2(unsigned long long& d, unsigned long long a) {
    asm("mul.rn.f32x2 %0,%0,%1;" : "+l"(d) : "l"(a));
}
__device__ __forceinline__ void cpasync16(uint32_t daddr, const void* g) {
    asm volatile("cp.async.cg.shared.global [%0],[%1],16;" ::"r"(daddr), "l"(g));
}
#define CP_COMMIT() asm volatile("cp.async.commit_group;")
#define CP_WAIT1()  asm volatile("cp.async.wait_group 1;")

// =============== kS: state = [x0,dc]@W_fc + pool@W_fc1 ; grid(4,32) x 128
__global__ void __launch_bounds__(128) kS(const float* __restrict__ X, const float* __restrict__ pool,
                                          const float* __restrict__ dc, const float* __restrict__ Wfc,
                                          const float* __restrict__ Wfc1) {
    __shared__ float sx[512 * 8], sp[512 * 8], sdc[8];
    int j0 = blockIdx.x * 128, b0 = blockIdx.y * 8, tid = threadIdx.x;
    for (int i = tid; i < 4096; i += 128) {
        int bb = i >> 9, e = i & 511;
        sx[e * 8 + bb] = X[(size_t)(b0 + bb) * (Nn * Dd) + e];
        sp[e * 8 + bb] = pool[(b0 + bb) * Dd + e];
    }
    if (tid < 8) sdc[tid] = dc[b0 + tid];
    __syncthreads();
    int j = j0 + tid;
    float acc[8] = {0, 0, 0, 0, 0, 0, 0, 0};
    for (int e = 0; e < 512; e++) {
        float w0 = Wfc[e * Dd + j], w1 = Wfc1[e * Dd + j];
        float4 a0 = *(const float4*)(sx + e * 8), a1 = *(const float4*)(sx + e * 8 + 4);
        float4 c0 = *(const float4*)(sp + e * 8), c1 = *(const float4*)(sp + e * 8 + 4);
        acc[0] += a0.x * w0 + c0.x * w1; acc[1] += a0.y * w0 + c0.y * w1;
        acc[2] += a0.z * w0 + c0.z * w1; acc[3] += a0.w * w0 + c0.w * w1;
        acc[4] += a1.x * w0 + c1.x * w1; acc[5] += a1.y * w0 + c1.y * w1;
        acc[6] += a1.z * w0 + c1.z * w1; acc[7] += a1.w * w0 + c1.w * w1;
    }
    float wl = Wfc[512 * Dd + j];
#pragma unroll
    for (int bb = 0; bb < 8; bb++) g_state[(b0 + bb) * Dd + j] = acc[bb] + sdc[bb] * wl;
}

// =============== kMM: Out = A@W ; 16 batches/CTA ; grid(4,16) x 128
__global__ void __launch_bounds__(128) kMM(const float* __restrict__ W, int mode) {
    __shared__ float sa[512 * 16];
    const float* A = mode ? g_mhaH : g_state;
    float* Out = mode ? g_mo : g_Qf;
    int j0 = blockIdx.x * 128, b0 = blockIdx.y * 16, tid = threadIdx.x;
    for (int i = tid; i < 8192; i += 128) sa[(i & 511) * 16 + (i >> 9)] = A[(b0 + (i >> 9)) * Dd + (i & 511)];
    __syncthreads();
    int j = j0 + tid;
    float acc[16];
#pragma unroll
    for (int k = 0; k < 16; k++) acc[k] = 0.f;
    for (int f = 0; f < 512; f++) {
        float wv = W[f * Dd + j];
#pragma unroll
        for (int q = 0; q < 4; q++) {
            float4 a = *(const float4*)(sa + f * 16 + q * 4);
            acc[q * 4 + 0] += a.x * wv; acc[q * 4 + 1] += a.y * wv;
            acc[q * 4 + 2] += a.z * wv; acc[q * 4 + 3] += a.w * wv;
        }
    }
#pragma unroll
    for (int bb = 0; bb < 16; bb++) Out[(b0 + bb) * Dd + j] = acc[bb];
}

// =============== kQt: Qt[b][h][e] ; 16 batches/CTA ; grid(4,16) x 128
__global__ void __launch_bounds__(128) kQt(const float* __restrict__ Wk) {
    __shared__ float sq[16 * 512];
    int e0 = blockIdx.x * 128, b0 = blockIdx.y * 16, tid = threadIdx.x;
    for (int i = tid; i < 8192; i += 128) sq[i] = g_Qf[(b0 + (i >> 9)) * Dd + (i & 511)];
    __syncthreads();
    int e = e0 + tid;
    const float* wrow = Wk + (size_t)e * Dd;
    for (int h = 0; h < 8; h++) {
        float acc[16];
#pragma unroll
        for (int k = 0; k < 16; k++) acc[k] = 0.f;
        const float* wr = wrow + h * 64;
#pragma unroll
        for (int d4 = 0; d4 < 16; d4++) {
            float4 wv = *(const float4*)(wr + d4 * 4);
#pragma unroll
            for (int bb = 0; bb < 16; bb++) {
                float4 q = *(const float4*)(sq + bb * 512 + h * 64 + d4 * 4);
                acc[bb] += wv.x * q.x + wv.y * q.y + wv.z * q.z + wv.w * q.w;
            }
        }
#pragma unroll
        for (int bb = 0; bb < 16; bb++) g_Qt[(size_t)(b0 + bb) * 4096 + h * 512 + e] = acc[bb] * NORM_MHA;
    }
}

// =============== kB: streaming pass 1 (cp.async 3-buffer, mask-skip, f32x2) ===============
// dyn smem layout (floats): xs[3*8192] | cpart[256] | pbuf[2*128] | s_m[8] | s_l[8] | s_scale[16] | s_any[2] | pad2 | mask[1000]
#define KB_SMEM_FLOATS 26124
__global__ void __launch_bounds__(512, 2) kB(const float* __restrict__ X, const int* __restrict__ mask) {
    extern __shared__ float sm[];
    float* xs = sm;
    float* cpart = sm + 24576;
    float* pbuf = sm + 24832;
    float* s_m = sm + 25088;
    float* s_l = sm + 25096;
    float* s_scale = sm + 25104;
    float* s_any = sm + 25120;
    int* smk = (int*)(sm + 25124);

    int b = blockIdx.x, tid = threadIdx.x, w = tid >> 5, lane = tid & 31;
    const float* Xb = X + (size_t)b * (Nn * Dd);
    for (int i = tid; i < Nn; i += 512) smk[i] = mask[b * Nn + i];
    if (tid < 8) { s_m[tid] = NEGINF; s_l[tid] = 0.f; }
    __syncthreads();

    int tg = w >> 2, qh = (w >> 1) & 1, eh = w & 1;
    int e_lo = eh * 256 + (lane << 2);
    unsigned long long qt2[2][8];
    {
        const float* Qtb = g_Qt + (size_t)b * 4096;
        float qv[4][8];
#pragma unroll
        for (int hh = 0; hh < 4; hh++) {
            int h = qh * 4 + hh;
            float4 a = *(const float4*)(Qtb + h * 512 + e_lo);
            float4 c = *(const float4*)(Qtb + h * 512 + e_lo + 128);
            qv[hh][0] = a.x; qv[hh][1] = a.y; qv[hh][2] = a.z; qv[hh][3] = a.w;
            qv[hh][4] = c.x; qv[hh][5] = c.y; qv[hh][6] = c.z; qv[hh][7] = c.w;
        }
#pragma unroll
        for (int e = 0; e < 8; e++) {
            qt2[0][e] = pack2(qv[0][e], qv[1][e]);
            qt2[1][e] = pack2(qv[2][e], qv[3][e]);
        }
    }

    int grp = tid >> 8, e2 = tid & 255;
    unsigned long long ys64[8];
#pragma unroll
    for (int h = 0; h < 8; h++) ys64[h] = 0ULL;

    uint32_t xs_sh = (uint32_t)__cvta_generic_to_shared(xs);

    // prologue: issue tile 0
    {
#pragma unroll
        for (int j = 0; j < 4; j++) {
            int i = tid + j * 512;
            int tok = i >> 7;
            if (!smk[tok]) cpasync16(xs_sh + i * 16, (const char*)Xb + (size_t)i * 16);
        }
        CP_COMMIT();
    }

    for (int t = 0; t < 63; t++) {
        int t0 = t * 16;
        int ntok = (t == 62) ? 8 : 16;
        int cur = t % 3, par = t & 1;
        // issue next tile
        if (t < 62) {
            int nt0 = t0 + 16;
            int nv = ((t == 61) ? 8 : 16) * 128;
            const char* src = (const char*)(Xb + (size_t)nt0 * 512);
            uint32_t dsh = xs_sh + ((t + 1) % 3) * 32768;
#pragma unroll
            for (int j = 0; j < 4; j++) {
                int i = tid + j * 512;
                if (i < nv) {
                    int tok = i >> 7;
                    if (!smk[nt0 + tok]) cpasync16(dsh + i * 16, src + (size_t)i * 16);
                }
            }
        }
        CP_COMMIT();
        CP_WAIT1();
        __syncthreads();
        // ---- phase 2: compat partials ----
        const float* xc = xs + cur * 8192;
        if (tid == 0) s_any[par] = 0.f;
        if (tg * 4 < ntok) {
#pragma unroll
            for (int k = 0; k < 4; k++) {
                int n = tg * 4 + k;
                if (smk[t0 + n]) continue;
                const float* row = xc + (n << 9);
                float4 xa = *(const float4*)(row + e_lo);
                float4 xb2 = *(const float4*)(row + e_lo + 128);
                unsigned long long av0 = 0, av1 = 0, xx;
                xx = pack2(xa.x, xa.x); ffma2(av0, xx, qt2[0][0]); ffma2(av1, xx, qt2[1][0]);
                xx = pack2(xa.y, xa.y); ffma2(av0, xx, qt2[0][1]); ffma2(av1, xx, qt2[1][1]);
                xx = pack2(xa.z, xa.z); ffma2(av0, xx, qt2[0][2]); ffma2(av1, xx, qt2[1][2]);
                xx = pack2(xa.w, xa.w); ffma2(av0, xx, qt2[0][3]); ffma2(av1, xx, qt2[1][3]);
                xx = pack2(xb2.x, xb2.x); ffma2(av0, xx, qt2[0][4]); ffma2(av1, xx, qt2[1][4]);
                xx = pack2(xb2.y, xb2.y); ffma2(av0, xx, qt2[0][5]); ffma2(av1, xx, qt2[1][5]);
                xx = pack2(xb2.z, xb2.z); ffma2(av0, xx, qt2[0][6]); ffma2(av1, xx, qt2[1][6]);
                xx = pack2(xb2.w, xb2.w); ffma2(av0, xx, qt2[0][7]); ffma2(av1, xx, qt2[1][7]);
                float a0, a1, a2, a3;
                unpack2(av0, a0, a1); unpack2(av1, a2, a3);
#pragma unroll
                for (int off = 16; off > 0; off >>= 1) {
                    a0 += __shfl_xor_sync(0xffffffffu, a0, off);
                    a1 += __shfl_xor_sync(0xffffffffu, a1, off);
                    a2 += __shfl_xor_sync(0xffffffffu, a2, off);
                    a3 += __shfl_xor_sync(0xffffffffu, a3, off);
                }
                if (lane == 0)
                    *(float4*)(cpart + (eh * 16 + n) * 8 + qh * 4) = make_float4(a0, a1, a2, a3);
            }
        }
        __syncthreads();
        // ---- phase 3: online softmax ----
        if (w < 8) {
            int h = w;
            float u = NEGINF;
            if (lane < ntok && smk[t0 + lane] == 0) u = cpart[lane * 8 + h] + cpart[128 + lane * 8 + h];
            float tmax = u;
#pragma unroll
            for (int off = 16; off > 0; off >>= 1) tmax = fmaxf(tmax, __shfl_xor_sync(0xffffffffu, tmax, off));
            float m_old = s_m[h], m_new = fmaxf(m_old, tmax);
            float p = (u != NEGINF) ? __expf(u - m_new) : 0.f;
            if (lane < 16) pbuf[par * 128 + lane * 8 + h] = p;
            float ps = p;
#pragma unroll
            for (int off = 16; off > 0; off >>= 1) ps += __shfl_xor_sync(0xffffffffu, ps, off);
            if (lane == 0) {
                float sc = 1.f;
                if (m_new > m_old) { sc = (m_old == NEGINF) ? 1.f : __expf(m_old - m_new); s_m[h] = m_new; }
                s_scale[par * 8 + h] = sc;
                s_l[h] = s_l[h] * sc + ps;
                if (sc != 1.f) s_any[par] = 1.f;
            }
        }
        __syncthreads();
        // ---- phase 4: ysum (runs into next iteration, 3-buffer makes this safe) ----
        if (s_any[par] != 0.f) {
#pragma unroll
            for (int h = 0; h < 8; h++) {
                float s = s_scale[par * 8 + h];
                fmul2(ys64[h], pack2(s, s));
            }
        }
        int kbeg = grp * 8, kend = min(kbeg + 8, ntok);
        const float* pb = pbuf + par * 128;
        for (int k = kbeg; k < kend; k++) {
            if (smk[t0 + k]) continue;
            unsigned long long xv = *(const unsigned long long*)(xc + (k << 9) + (e2 << 1));
            float4 p0 = *(const float4*)(pb + (k << 3));
            float4 p1 = *(const float4*)(pb + (k << 3) + 4);
            ffma2(ys64[0], xv, pack2(p0.x, p0.x));
            ffma2(ys64[1], xv, pack2(p0.y, p0.y));
            ffma2(ys64[2], xv, pack2(p0.z, p0.z));
            ffma2(ys64[3], xv, pack2(p0.w, p0.w));
            ffma2(ys64[4], xv, pack2(p1.x, p1.x));
            ffma2(ys64[5], xv, pack2(p1.y, p1.y));
            ffma2(ys64[6], xv, pack2(p1.z, p1.z));
            ffma2(ys64[7], xv, pack2(p1.w, p1.w));
        }
    }
    __syncthreads();
    // epilogue: merge two token-group partials via xs buf0, write out
    float* buf = xs;
    if (grp == 0) {
#pragma unroll
        for (int h = 0; h < 8; h++) {
            float a, bv;
            unpack2(ys64[h], a, bv);
            *(float2*)(buf + h * 512 + (e2 << 1)) = make_float2(a, bv);
        }
    }
    __syncthreads();
    if (grp == 1) {
#pragma unroll
        for (int h = 0; h < 8; h++) {
            float a, bv;
            unpack2(ys64[h], a, bv);
            float2 v = *(float2*)(buf + h * 512 + (e2 << 1));
            v.x += a; v.y += bv;
            *(float2*)(buf + h * 512 + (e2 << 1)) = v;
        }
    }
    __syncthreads();
    float* yo = g_ysum + (size_t)b * 4096;
    for (int i = tid; i < 4096; i += 512) yo[i] = buf[i];
    if (tid < 8) g_l[b * 8 + tid] = s_l[tid];
}

// =============== kV: mhaH = (ysum/l)@Wv ; grid(4,32) x 128
__global__ void __launch_bounds__(128) kV(const float* __restrict__ Wv) {
    __shared__ float syc[2 * 4096];
    __shared__ float slinv[16];
    int h0 = blockIdx.x * 2, b0 = blockIdx.y * 8, tid = threadIdx.x;
    if (tid < 16) slinv[tid] = 1.f / g_l[(b0 + (tid >> 1)) * 8 + h0 + (tid & 1)];
    __syncthreads();
    for (int i = tid; i < 8192; i += 128) {
        int hl = i >> 12, bb = (i >> 9) & 7, e = i & 511;
        syc[hl * 4096 + e * 8 + bb] = g_ysum[(size_t)(b0 + bb) * 4096 + (h0 + hl) * 512 + e] * slinv[bb * 2 + hl];
    }
    __syncthreads();
    int j = blockIdx.x * 128 + tid, hl = tid >> 6;
    const float* base = syc + hl * 4096;
    float acc[8] = {0, 0, 0, 0, 0, 0, 0, 0};
    for (int e = 0; e < 512; e++) {
        float wv = Wv[e * Dd + j];
        float4 y0 = *(const float4*)(base + e * 8), y1 = *(const float4*)(base + e * 8 + 4);
        acc[0] += y0.x * wv; acc[1] += y0.y * wv; acc[2] += y0.z * wv; acc[3] += y0.w * wv;
        acc[4] += y1.x * wv; acc[5] += y1.y * wv; acc[6] += y1.z * wv; acc[7] += y1.w * wv;
    }
#pragma unroll
    for (int bb = 0; bb < 8; bb++) g_mhaH[(b0 + bb) * Dd + j] = acc[bb];
}

// =============== kZ: z = norm_ptr * Wkp@mo ; 16 batches/CTA ; grid(4,16) x 128
__global__ void __launch_bounds__(128) kZ(const float* __restrict__ Wkp) {
    __shared__ float smo[512 * 16];
    int e0 = blockIdx.x * 128, b0 = blockIdx.y * 16, tid = threadIdx.x;
    for (int i = tid; i < 8192; i += 128) smo[(i & 511) * 16 + (i >> 9)] = g_mo[(b0 + (i >> 9)) * Dd + (i & 511)];
    __syncthreads();
    int e = e0 + tid;
    const float* wrow = Wkp + (size_t)e * Dd;
    float acc[16];
#pragma unroll
    for (int k = 0; k < 16; k++) acc[k] = 0.f;
    for (int f = 0; f < 512; f++) {
        float wv = wrow[f];
#pragma unroll
        for (int q = 0; q < 4; q++) {
            float4 m = *(const float4*)(smo + f * 16 + q * 4);
            acc[q * 4 + 0] += m.x * wv; acc[q * 4 + 1] += m.y * wv;
            acc[q * 4 + 2] += m.z * wv; acc[q * 4 + 3] += m.w * wv;
        }
    }
#pragma unroll
    for (int bb = 0; bb < 16; bb++) g_z[(b0 + bb) * Dd + e] = acc[bb] * NORM_PTR;
}

// =============== kD: streaming pass 2 — mask-skip, unroll x2 ===============
__global__ void __launch_bounds__(512, 2) kD(const float* __restrict__ X, const int* __restrict__ mask,
                                             float* __restrict__ out) {
    __shared__ float tvals[Nn];
    __shared__ int smk[Nn];
    __shared__ float red[16];
    __shared__ float bcast;
    int b = blockIdx.x, tid = threadIdx.x, w = tid >> 5, lane = tid & 31;
    for (int i = tid; i < Nn; i += 512) smk[i] = mask[b * Nn + i];
    const float* zb = g_z + b * Dd;
    float4 z0 = *(const float4*)(zb + lane * 4);
    float4 z1 = *(const float4*)(zb + 128 + lane * 4);
    float4 z2 = *(const float4*)(zb + 256 + lane * 4);
    float4 z3 = *(const float4*)(zb + 384 + lane * 4);
    const float* Xb = X + (size_t)b * (Nn * Dd);
    __syncthreads();
    float wmax = NEGINF;
    for (int t = 0; t < 31; t++) {
        int n0 = w + 32 * t, n1 = n0 + 16;
        int m0 = smk[n0], m1 = smk[n1];
        float acc0 = 0.f, acc1 = 0.f;
        if (!m0) {
            const float* row = Xb + (size_t)n0 * Dd;
            float4 x0 = *(const float4*)(row + lane * 4);
            float4 x1 = *(const float4*)(row + 128 + lane * 4);
            float4 x2 = *(const float4*)(row + 256 + lane * 4);
            float4 x3 = *(const float4*)(row + 384 + lane * 4);
            acc0 = x0.x * z0.x + x0.y * z0.y + x0.z * z0.z + x0.w * z0.w
                 + x1.x * z1.x + x1.y * z1.y + x1.z * z1.z + x1.w * z1.w
                 + x2.x * z2.x + x2.y * z2.y + x2.z * z2.z + x2.w * z2.w
                 + x3.x * z3.x + x3.y * z3.y + x3.z * z3.z + x3.w * z3.w;
        }
        if (!m1) {
            const float* row = Xb + (size_t)n1 * Dd;
            float4 x0 = *(const float4*)(row + lane * 4);
            float4 x1 = *(const float4*)(row + 128 + lane * 4);
            float4 x2 = *(const float4*)(row + 256 + lane * 4);
            float4 x3 = *(const float4*)(row + 384 + lane * 4);
            acc1 = x0.x * z0.x + x0.y * z0.y + x0.z * z0.z + x0.w * z0.w
                 + x1.x * z1.x + x1.y * z1.y + x1.z * z1.z + x1.w * z1.w
                 + x2.x * z2.x + x2.y * z2.y + x2.z * z2.z + x2.w * z2.w
                 + x3.x * z3.x + x3.y * z3.y + x3.z * z3.z + x3.w * z3.w;
        }
        if (!m0 || !m1) {
#pragma unroll
            for (int off = 16; off > 0; off >>= 1) {
                acc0 += __shfl_xor_sync(0xffffffffu, acc0, off);
                acc1 += __shfl_xor_sync(0xffffffffu, acc1, off);
            }
        }
        float tv0 = m0 ? NEGINF : tanhf(acc0) * 10.f;
        float tv1 = m1 ? NEGINF : tanhf(acc1) * 10.f;
        if (lane == 0) { tvals[n0] = tv0; tvals[n1] = tv1; }
        wmax = fmaxf(wmax, fmaxf(tv0, tv1));
    }
    if (w < 8) {  // tail tokens 992..999
        int n = 992 + w;
        int m0 = smk[n];
        float acc0 = 0.f;
        if (!m0) {
            const float* row = Xb + (size_t)n * Dd;
            float4 x0 = *(const float4*)(row + lane * 4);
            float4 x1 = *(const float4*)(row + 128 + lane * 4);
            float4 x2 = *(const float4*)(row + 256 + lane * 4);
            float4 x3 = *(const float4*)(row + 384 + lane * 4);
            acc0 = x0.x * z0.x + x0.y * z0.y + x0.z * z0.z + x0.w * z0.w
                 + x1.x * z1.x + x1.y * z1.y + x1.z * z1.z + x1.w * z1.w
                 + x2.x * z2.x + x2.y * z2.y + x2.z * z2.z + x2.w * z2.w
                 + x3.x * z3.x + x3.y * z3.y + x3.z * z3.z + x3.w * z3.w;
#pragma unroll
            for (int off = 16; off > 0; off >>= 1) acc0 += __shfl_xor_sync(0xffffffffu, acc0, off);
        }
        float tv0 = m0 ? NEGINF : tanhf(acc0) * 10.f;
        if (lane == 0) tvals[n] = tv0;
        wmax = fmaxf(wmax, tv0);
    }
    if (lane == 0) red[w] = wmax;
    __syncthreads();
    if (tid == 0) {
        float m = red[0];
#pragma unroll
        for (int i = 1; i < 16; i++) m = fmaxf(m, red[i]);
        bcast = m;
    }
    __syncthreads();
    float gmax = bcast;
    float t0v = tvals[tid];
    float ev0 = (t0v == NEGINF) ? 0.f : __expf(t0v - gmax);
    int n1 = tid + 512;
    float ev1 = 0.f;
    if (n1 < Nn) {
        float t1v = tvals[n1];
        ev1 = (t1v == NEGINF) ? 0.f : __expf(t1v - gmax);
    }
    float ps = ev0 + ev1;
#pragma unroll
    for (int off = 16; off > 0; off >>= 1) ps += __shfl_xor_sync(0xffffffffu, ps, off);
    __syncthreads();
    if (lane == 0) red[w] = ps;
    __syncthreads();
    if (tid == 0) {
        float s = 0.f;
#pragma unroll
        for (int i = 0; i < 16; i++) s += red[i];
        bcast = 1.f / s;
    }
    __syncthreads();
    float inv = bcast;
    out[b * Nn + tid] = ev0 * inv;
    if (n1 < Nn) out[b * Nn + n1] = ev1 * inv;
}

extern "C" void kernel_launch(void* const* d_in, const int* in_sizes, int n_in,
                              void* d_out, int out_size) {
    const float* X    = (const float*)d_in[0];
    const float* pool = (const float*)d_in[1];
    const float* dc   = (const float*)d_in[2];
    const int*   mask = (const int*)d_in[3];
    const float* Wfc  = (const float*)d_in[4];
    const float* Wfc1 = (const float*)d_in[5];
    const float* Wq   = (const float*)d_in[6];
    const float* Wkm  = (const float*)d_in[7];
    const float* Wv   = (const float*)d_in[8];
    const float* Wo   = (const float*)d_in[9];
    const float* Wkp  = (const float*)d_in[10];
    float* out = (float*)d_out;
    const int KB_SMEM = KB_SMEM_FLOATS * 4;
    cudaFuncSetAttribute(kB, cudaFuncAttributeMaxDynamicSharedMemorySize, KB_SMEM);
    kS<<<dim3(4, 32), 128>>>(X, pool, dc, Wfc, Wfc1);
    kMM<<<dim3(4, 16), 128>>>(Wq, 0);
    kQt<<<dim3(4, 16), 128>>>(Wkm);
    kB<<<256, 512, KB_SMEM>>>(X, mask);
    kV<<<dim3(4, 32), 128>>>(Wv);
    kMM<<<dim3(4, 16), 128>>>(Wo, 1);
    kZ<<<dim3(4, 16), 128>>>(Wkp);
    kD<<<256, 512>>>(X, mask, out);
}